// round 3
// baseline (speedup 1.0000x reference)
#include <cuda_runtime.h>

#define NVV 100000
#define NSS 50000
#define DGG 5
#define DSS 6
#define HH  64
#define OUTD 8

// ---------------- scratch (device globals; no allocations) ----------------
__device__ float d_deg_v[NVV];
__device__ float d_h1[NVV * DGG];
__device__ float d_h2[NVV * DGG];
__device__ float d_gx[NVV * HH];
__device__ float d_agg[NSS * HH];
__device__ float d_ssum[NSS * HH];
__device__ float d_cnt[NSS];
__device__ float d_deg_s[NSS];
__device__ float d_sx[NSS * HH];
__device__ float d_sx2[NSS * HH];
__device__ float d_hA[NSS * HH];
__device__ float d_hB[NSS * HH];
__device__ float d_acc[NSS * HH];
__device__ int   d_is64;

// ---------------- dtype detection ----------------
// Reference casts edge indices to int64, but if JAX x64 is disabled they are
// int32. For int64 (values < 2^31, nonnegative) every odd 32-bit word is 0.
// For int32 random indices in [0,100000) the odds of 128 consecutive odd
// words all being zero are ~(1e-5)^128 ~ 0.
__global__ void k_detect(const int* __restrict__ w) {
    int is64 = 1;
#pragma unroll 1
    for (int i = 0; i < 128; i++) {
        if (w[2 * i + 1] != 0) { is64 = 0; break; }
    }
    d_is64 = is64;
}

__device__ __forceinline__ void load_edge(const void* ei, int E, int e, int is64,
                                          int& s, int& d) {
    if (is64) {
        const long long* p = (const long long*)ei;
        s = (int)p[e];
        d = (int)p[(long long)E + e];
    } else {
        const int* p = (const int*)ei;
        s = p[e];
        d = p[E + e];
    }
}

// ---------------- utility ----------------
__global__ void k_zero(float* __restrict__ p, int n) {
    int i = blockIdx.x * blockDim.x + threadIdx.x;
    if (i < n) p[i] = 0.0f;
}

__global__ void k_deg(const void* __restrict__ ei, int E, float* __restrict__ deg) {
    int e = blockIdx.x * blockDim.x + threadIdx.x;
    if (e >= E) return;
    int dst;
    if (d_is64) dst = (int)((const long long*)ei)[(long long)E + e];
    else        dst = ((const int*)ei)[E + e];
    atomicAdd(&deg[dst], 1.0f);
}

__global__ void k_dinv(float* __restrict__ deg, int n) {
    int i = blockIdx.x * blockDim.x + threadIdx.x;
    if (i >= n) return;
    float d = deg[i];
    deg[i] = (d > 0.0f) ? rsqrtf(d) : 0.0f;
}

// ---------------- 5-dim normalized propagation (TAG1) ----------------
__global__ void k_prop5(const void* __restrict__ ei, int E,
                        const float* __restrict__ dinv,
                        const float* __restrict__ hin,
                        float* __restrict__ hout) {
    int e = blockIdx.x * blockDim.x + threadIdx.x;
    if (e >= E) return;
    int is64 = d_is64;
    int s, d;
    load_edge(ei, E, e, is64, s, d);
    float norm = dinv[s] * dinv[d];
    if (norm == 0.0f) return;
    const float* src = hin + (long long)s * DGG;
    float* dst = hout + (long long)d * DGG;
#pragma unroll
    for (int f = 0; f < DGG; f++) atomicAdd(dst + f, src[f] * norm);
}

// ---------------- 64-dim normalized propagation (TAG2) ----------------
// thread = (edge, 4-feature chunk); 16 threads/edge -> coalesced 256B gather.
__global__ void k_prop64(const void* __restrict__ ei, int E,
                         const float* __restrict__ dinv,
                         const float* __restrict__ hin,
                         float* __restrict__ hout) {
    long long t = (long long)blockIdx.x * blockDim.x + threadIdx.x;
    int e = (int)(t >> 4);
    if (e >= E) return;
    int c = ((int)t & 15) << 2;
    int is64 = d_is64;
    int s, d;
    load_edge(ei, E, e, is64, s, d);
    float norm = dinv[s] * dinv[d];
    if (norm == 0.0f) return;
    float4 v = *(const float4*)(hin + (long long)s * HH + c);
    float* o = hout + (long long)d * HH + c;
    atomicAdd(o + 0, v.x * norm);
    atomicAdd(o + 1, v.y * norm);
    atomicAdd(o + 2, v.z * norm);
    atomicAdd(o + 3, v.w * norm);
}

// ---------------- GraphConv aggregation: agg[dst] += w[e]*gx[src] ----------------
__global__ void k_gc_agg(const void* __restrict__ ei, int E,
                         const float* __restrict__ attr,
                         const float* __restrict__ gx,
                         float* __restrict__ agg) {
    long long t = (long long)blockIdx.x * blockDim.x + threadIdx.x;
    int e = (int)(t >> 4);
    if (e >= E) return;
    int c = ((int)t & 15) << 2;
    int is64 = d_is64;
    int s, d;
    load_edge(ei, E, e, is64, s, d);
    float w = attr[e];
    float4 v = *(const float4*)(gx + (long long)s * HH + c);
    float* o = agg + (long long)d * HH + c;
    atomicAdd(o + 0, v.x * w);
    atomicAdd(o + 1, v.y * w);
    atomicAdd(o + 2, v.z * w);
    atomicAdd(o + 3, v.w * w);
}

// ---------------- SAGE aggregation: ssum[dst] += gx[src]; cnt[dst] += 1 ----------------
__global__ void k_sage_agg(const void* __restrict__ ei, int E,
                           const float* __restrict__ gx,
                           float* __restrict__ ssum,
                           float* __restrict__ cnt) {
    long long t = (long long)blockIdx.x * blockDim.x + threadIdx.x;
    int e = (int)(t >> 4);
    if (e >= E) return;
    int c = ((int)t & 15) << 2;
    int is64 = d_is64;
    int s, d;
    load_edge(ei, E, e, is64, s, d);
    float4 v = *(const float4*)(gx + (long long)s * HH + c);
    float* o = ssum + (long long)d * HH + c;
    atomicAdd(o + 0, v.x);
    atomicAdd(o + 1, v.y);
    atomicAdd(o + 2, v.z);
    atomicAdd(o + 3, v.w);
    if (c == 0) atomicAdd(&cnt[d], 1.0f);
}

// ---------------- TAG1 dense: gx = relu(x@W0 + h1@W1 + h2@W2 + b) ----------------
__global__ void k_tag1_dense(const float* __restrict__ x,
                             const float* __restrict__ h1,
                             const float* __restrict__ h2,
                             const float* __restrict__ W,  // [3][5][64]
                             const float* __restrict__ b,
                             float* __restrict__ gx, int n) {
    __shared__ float sW[3 * DGG * HH];  // 960
    __shared__ float sb[HH];
    __shared__ float sX[32][16];        // 15 feats padded to 16
    int t = threadIdx.x;
    int base = blockIdx.x * 32;
    for (int i = t; i < 3 * DGG * HH; i += 256) sW[i] = W[i];
    if (t < HH) sb[t] = b[t];
    for (int i = t; i < 32 * 15; i += 256) {
        int row = i / 15, f = i - row * 15;
        int r = base + row;
        float v = 0.0f;
        if (r < n) {
            if (f < 5)       v = x [(long long)r * DGG + f];
            else if (f < 10) v = h1[(long long)r * DGG + (f - 5)];
            else             v = h2[(long long)r * DGG + (f - 10)];
        }
        sX[row][f] = v;
    }
    __syncthreads();
    int c = t & 63, ry = t >> 6;
#pragma unroll
    for (int j = 0; j < 8; j++) {
        int rl = ry + 4 * j;
        int r = base + rl;
        if (r >= n) continue;
        float acc = sb[c];
#pragma unroll
        for (int f = 0; f < DGG; f++) acc += sX[rl][f]      * sW[f * HH + c];
#pragma unroll
        for (int f = 0; f < DGG; f++) acc += sX[rl][5 + f]  * sW[(DGG + f) * HH + c];
#pragma unroll
        for (int f = 0; f < DGG; f++) acc += sX[rl][10 + f] * sW[(2 * DGG + f) * HH + c];
        gx[(long long)r * HH + c] = fmaxf(acc, 0.0f);
    }
}

// ---------------- GraphConv combine: sx = relu(agg@Wrel + b + state_x@Wroot) ----------------
__global__ void k_gc_comb(const float* __restrict__ agg,
                          const float* __restrict__ Wrel,
                          const float* __restrict__ b,
                          const float* __restrict__ statex,
                          const float* __restrict__ Wroot,
                          float* __restrict__ sx, int n) {
    __shared__ float sW1[HH * HH];
    __shared__ float sW2[DSS * HH];
    __shared__ float sb[HH];
    __shared__ float sA[32][HH];
    __shared__ float sS[32][8];
    int t = threadIdx.x;
    int base = blockIdx.x * 32;
    for (int i = t; i < HH * HH; i += 256) sW1[i] = Wrel[i];
    for (int i = t; i < DSS * HH; i += 256) sW2[i] = Wroot[i];
    if (t < HH) sb[t] = b[t];
    for (int i = t; i < 32 * HH; i += 256) {
        int row = i >> 6, col = i & 63, r = base + row;
        sA[row][col] = (r < n) ? agg[(long long)r * HH + col] : 0.0f;
    }
    for (int i = t; i < 32 * DSS; i += 256) {
        int row = i / DSS, col = i - row * DSS, r = base + row;
        sS[row][col] = (r < n) ? statex[(long long)r * DSS + col] : 0.0f;
    }
    __syncthreads();
    int c = t & 63, ry = t >> 6;
#pragma unroll
    for (int j = 0; j < 8; j++) {
        int rl = ry + 4 * j;
        int r = base + rl;
        if (r >= n) continue;
        float acc = sb[c];
#pragma unroll
        for (int k = 0; k < HH; k++) acc += sA[rl][k] * sW1[k * HH + c];
#pragma unroll
        for (int k = 0; k < DSS; k++) acc += sS[rl][k] * sW2[k * HH + c];
        sx[(long long)r * HH + c] = fmaxf(acc, 0.0f);
    }
}

// ---------------- SAGE combine: sx2 = relu(mean@Wl + bl + sx@Wr) ----------------
__global__ void k_sage_comb(const float* __restrict__ ssum,
                            const float* __restrict__ cnt,
                            const float* __restrict__ Wl,
                            const float* __restrict__ bl,
                            const float* __restrict__ sxin,
                            const float* __restrict__ Wr,
                            float* __restrict__ sx2, int n) {
    __shared__ float sW[HH * HH];
    __shared__ float sA[32][HH];  // mean
    __shared__ float sB[32][HH];  // sx
    int t = threadIdx.x;
    int base = blockIdx.x * 32;
    for (int i = t; i < HH * HH; i += 256) sW[i] = Wl[i];
    for (int i = t; i < 32 * HH; i += 256) {
        int row = i >> 6, col = i & 63, r = base + row;
        float vA = 0.0f, vB = 0.0f;
        if (r < n) {
            float cinv = 1.0f / fmaxf(cnt[r], 1.0f);
            vA = ssum[(long long)r * HH + col] * cinv;
            vB = sxin[(long long)r * HH + col];
        }
        sA[row][col] = vA;
        sB[row][col] = vB;
    }
    __syncthreads();
    int c = t & 63, ry = t >> 6;
    float acc[8];
#pragma unroll
    for (int j = 0; j < 8; j++) acc[j] = __ldg(&bl[c]);
#pragma unroll
    for (int j = 0; j < 8; j++) {
        int rl = ry + 4 * j;
#pragma unroll
        for (int k = 0; k < HH; k++) acc[j] += sA[rl][k] * sW[k * HH + c];
    }
    __syncthreads();
    for (int i = t; i < HH * HH; i += 256) sW[i] = Wr[i];
    __syncthreads();
#pragma unroll
    for (int j = 0; j < 8; j++) {
        int rl = ry + 4 * j;
        int r = base + rl;
#pragma unroll
        for (int k = 0; k < HH; k++) acc[j] += sB[rl][k] * sW[k * HH + c];
        if (r < n) sx2[(long long)r * HH + c] = fmaxf(acc[j], 0.0f);
    }
}

// ---------------- acc = X@W (+b) or acc += X@W ----------------
__global__ void k_mm(const float* __restrict__ X, const float* __restrict__ W,
                     const float* __restrict__ b, float* __restrict__ out,
                     int n, int add) {
    __shared__ float sW[HH * HH];
    __shared__ float sX[32][HH];
    __shared__ float sb[HH];
    int t = threadIdx.x;
    int base = blockIdx.x * 32;
    for (int i = t; i < HH * HH; i += 256) sW[i] = W[i];
    if (t < HH) sb[t] = b ? b[t] : 0.0f;
    for (int i = t; i < 32 * HH; i += 256) {
        int row = i >> 6, col = i & 63, r = base + row;
        sX[row][col] = (r < n) ? X[(long long)r * HH + col] : 0.0f;
    }
    __syncthreads();
    int c = t & 63, ry = t >> 6;
#pragma unroll
    for (int j = 0; j < 8; j++) {
        int rl = ry + 4 * j;
        int r = base + rl;
        if (r >= n) continue;
        float acc = sb[c];
#pragma unroll
        for (int k = 0; k < HH; k++) acc += sX[rl][k] * sW[k * HH + c];
        long long oi = (long long)r * HH + c;
        out[oi] = add ? (out[oi] + acc) : acc;
    }
}

// ---------------- final: out = relu(acc)@linW + linb ----------------
__global__ void k_final(const float* __restrict__ acc,
                        const float* __restrict__ W,
                        const float* __restrict__ b,
                        float* __restrict__ out, int n) {
    __shared__ float sA[32][HH];
    __shared__ float sW[HH * OUTD];
    __shared__ float sb[OUTD];
    int t = threadIdx.x;
    int base = blockIdx.x * 32;
    for (int i = t; i < HH * OUTD; i += 256) sW[i] = W[i];
    if (t < OUTD) sb[t] = b[t];
    for (int i = t; i < 32 * HH; i += 256) {
        int row = i >> 6, col = i & 63, r = base + row;
        sA[row][col] = (r < n) ? fmaxf(acc[(long long)r * HH + col], 0.0f) : 0.0f;
    }
    __syncthreads();
    int o = t & 7, ry = t >> 3;
    int r = base + ry;
    if (r >= n) return;
    float a = sb[o];
#pragma unroll
    for (int k = 0; k < HH; k++) a += sA[ry][k] * sW[k * OUTD + o];
    out[(long long)r * OUTD + o] = a;
}

// ---------------- host ----------------
static inline int gs(long long n, int bs) { return (int)((n + bs - 1) / bs); }

extern "C" void kernel_launch(void* const* d_in, const int* in_sizes, int n_in,
                              void* d_out, int out_size) {
    const float* game_x  = (const float*)d_in[0];
    const float* state_x = (const float*)d_in[1];
    const void*  ei_vv   = d_in[2];
    const void*  ei_h    = d_in[3];
    const float* attr_h  = (const float*)d_in[4];
    const void*  ei_in   = d_in[5];
    const void*  ei_ss   = d_in[6];
    const float* tag1W   = (const float*)d_in[7];
    const float* tag1b   = (const float*)d_in[8];
    const float* tag2W   = (const float*)d_in[9];
    const float* tag2b   = (const float*)d_in[10];
    const float* Wrel    = (const float*)d_in[11];
    const float* bgc     = (const float*)d_in[12];
    const float* Wroot   = (const float*)d_in[13];
    const float* Wl      = (const float*)d_in[14];
    const float* bl      = (const float*)d_in[15];
    const float* Wr      = (const float*)d_in[16];
    const float* linW    = (const float*)d_in[17];
    const float* linb    = (const float*)d_in[18];
    float* out = (float*)d_out;

    int nv  = in_sizes[0] / DGG;   // 100000
    int ns  = in_sizes[1] / DSS;   // 50000
    int Evv = in_sizes[2] / 2;
    int Eh  = in_sizes[3] / 2;
    int Ein = in_sizes[5] / 2;
    int Ess = in_sizes[6] / 2;

    float *deg_v, *h1, *h2, *gx, *agg, *ssum, *cnt, *deg_s, *sx, *sx2, *hA, *hB, *acc;
    cudaGetSymbolAddress((void**)&deg_v, d_deg_v);
    cudaGetSymbolAddress((void**)&h1, d_h1);
    cudaGetSymbolAddress((void**)&h2, d_h2);
    cudaGetSymbolAddress((void**)&gx, d_gx);
    cudaGetSymbolAddress((void**)&agg, d_agg);
    cudaGetSymbolAddress((void**)&ssum, d_ssum);
    cudaGetSymbolAddress((void**)&cnt, d_cnt);
    cudaGetSymbolAddress((void**)&deg_s, d_deg_s);
    cudaGetSymbolAddress((void**)&sx, d_sx);
    cudaGetSymbolAddress((void**)&sx2, d_sx2);
    cudaGetSymbolAddress((void**)&hA, d_hA);
    cudaGetSymbolAddress((void**)&hB, d_hB);
    cudaGetSymbolAddress((void**)&acc, d_acc);

    const int BS = 256;

    // dtype probe
    k_detect<<<1, 1>>>((const int*)ei_vv);

    // ---- TAG1 on v-v graph ----
    k_zero<<<gs(nv, BS), BS>>>(deg_v, nv);
    k_deg<<<gs(Evv, BS), BS>>>(ei_vv, Evv, deg_v);
    k_dinv<<<gs(nv, BS), BS>>>(deg_v, nv);

    k_zero<<<gs((long long)nv * DGG, BS), BS>>>(h1, nv * DGG);
    k_prop5<<<gs(Evv, BS), BS>>>(ei_vv, Evv, deg_v, game_x, h1);
    k_zero<<<gs((long long)nv * DGG, BS), BS>>>(h2, nv * DGG);
    k_prop5<<<gs(Evv, BS), BS>>>(ei_vv, Evv, deg_v, h1, h2);
    k_tag1_dense<<<gs(nv, 32), BS>>>(game_x, h1, h2, tag1W, tag1b, gx, nv);

    // ---- GraphConv + SAGE aggregations ----
    k_zero<<<gs((long long)ns * HH, BS), BS>>>(agg, ns * HH);
    k_zero<<<gs((long long)ns * HH, BS), BS>>>(ssum, ns * HH);
    k_zero<<<gs(ns, BS), BS>>>(cnt, ns);
    k_gc_agg<<<gs((long long)Eh * 16, BS), BS>>>(ei_h, Eh, attr_h, gx, agg);
    k_sage_agg<<<gs((long long)Ein * 16, BS), BS>>>(ei_in, Ein, gx, ssum, cnt);

    k_gc_comb<<<gs(ns, 32), BS>>>(agg, Wrel, bgc, state_x, Wroot, sx, ns);
    k_sage_comb<<<gs(ns, 32), BS>>>(ssum, cnt, Wl, bl, sx, Wr, sx2, ns);

    // ---- TAG2 on s-s graph ----
    k_zero<<<gs(ns, BS), BS>>>(deg_s, ns);
    k_deg<<<gs(Ess, BS), BS>>>(ei_ss, Ess, deg_s);
    k_dinv<<<gs(ns, BS), BS>>>(deg_s, ns);

    // acc = sx2@W0 + b
    k_mm<<<gs(ns, 32), BS>>>(sx2, tag2W, tag2b, acc, ns, 0);

    k_zero<<<gs((long long)ns * HH, BS), BS>>>(hA, ns * HH);
    k_prop64<<<gs((long long)Ess * 16, BS), BS>>>(ei_ss, Ess, deg_s, sx2, hA);
    k_mm<<<gs(ns, 32), BS>>>(hA, tag2W + 1 * HH * HH, (const float*)0, acc, ns, 1);

    k_zero<<<gs((long long)ns * HH, BS), BS>>>(hB, ns * HH);
    k_prop64<<<gs((long long)Ess * 16, BS), BS>>>(ei_ss, Ess, deg_s, hA, hB);
    k_mm<<<gs(ns, 32), BS>>>(hB, tag2W + 2 * HH * HH, (const float*)0, acc, ns, 1);

    k_zero<<<gs((long long)ns * HH, BS), BS>>>(hA, ns * HH);
    k_prop64<<<gs((long long)Ess * 16, BS), BS>>>(ei_ss, Ess, deg_s, hB, hA);
    k_mm<<<gs(ns, 32), BS>>>(hA, tag2W + 3 * HH * HH, (const float*)0, acc, ns, 1);

    // ---- final linear ----
    k_final<<<gs(ns, 32), BS>>>(acc, linW, linb, out, ns);
}

// round 4
// speedup vs baseline: 1.3706x; 1.3706x over previous
#include <cuda_runtime.h>

#define NVV 100000
#define NSS 50000
#define DGG 5
#define DSS 6
#define HH  64
#define OUTD 8

// ---------------- scratch (device globals; no allocations) ----------------
__device__ __align__(16) float d_deg_v[NVV];
__device__ __align__(16) float d_h1[NVV * DGG];
__device__ __align__(16) float d_h2[NVV * DGG];
__device__ __align__(16) float d_gx[NVV * HH];
__device__ __align__(16) float d_agg[NSS * HH];
__device__ __align__(16) float d_ssum[NSS * HH];
__device__ __align__(16) float d_cnt[NSS];
__device__ __align__(16) float d_deg_s[NSS];
__device__ __align__(16) float d_sx[NSS * HH];
__device__ __align__(16) float d_sx2[NSS * HH];
__device__ __align__(16) float d_hA[NSS * HH];
__device__ __align__(16) float d_hB[NSS * HH];
__device__ __align__(16) float d_hC[NSS * HH];
__device__ __align__(16) float d_acc[NSS * HH];
__device__ int   d_is64;

// ---------------- vector reduction helper ----------------
__device__ __forceinline__ void red4(float* a, float x, float y, float z, float w) {
    asm volatile("red.global.add.v4.f32 [%0], {%1,%2,%3,%4};"
                 :: "l"(a), "f"(x), "f"(y), "f"(z), "f"(w) : "memory");
}

// ---------------- dtype detection (parallel, 1 warp) ----------------
// Reference casts edge indices to int64; with JAX x64 disabled they are int32.
// For int64 values < 2^31 every odd 32-bit word is 0. For int32 random
// indices the odds of 128 consecutive odd words all being zero are ~0.
__global__ void k_detect(const int* __restrict__ w) {
    int lane = threadIdx.x;
    int bad = 0;
    for (int i = lane; i < 128; i += 32)
        if (w[2 * i + 1] != 0) bad = 1;
    unsigned m = __ballot_sync(0xffffffffu, bad);
    if (lane == 0) d_is64 = (m == 0u) ? 1 : 0;
}

__device__ __forceinline__ void load_edge(const void* ei, int E, int e, int is64,
                                          int& s, int& d) {
    if (is64) {
        const long long* p = (const long long*)ei;
        s = (int)p[e];
        d = (int)p[(long long)E + e];
    } else {
        const int* p = (const int*)ei;
        s = p[e];
        d = p[E + e];
    }
}

// ---------------- fused zeroing of all scratch (float4 stores) ----------------
#define Z_DEGV (NVV / 4)
#define Z_H1   (NVV * DGG / 4)
#define Z_H2   (NVV * DGG / 4)
#define Z_BIG  (NSS * HH / 4)
#define Z_CNT  (NSS / 4)
#define Z_DEGS (NSS / 4)
#define Z_TOTAL (Z_DEGV + Z_H1 + Z_H2 + 5 * Z_BIG + Z_CNT + Z_DEGS)

__global__ void k_zero_all() {
    int i = blockIdx.x * blockDim.x + threadIdx.x;
    if (i >= Z_TOTAL) return;
    float4 z = make_float4(0.f, 0.f, 0.f, 0.f);
    if (i < Z_DEGV) { ((float4*)d_deg_v)[i] = z; return; } i -= Z_DEGV;
    if (i < Z_H1)   { ((float4*)d_h1)[i]    = z; return; } i -= Z_H1;
    if (i < Z_H2)   { ((float4*)d_h2)[i]    = z; return; } i -= Z_H2;
    if (i < Z_BIG)  { ((float4*)d_agg)[i]   = z; return; } i -= Z_BIG;
    if (i < Z_BIG)  { ((float4*)d_ssum)[i]  = z; return; } i -= Z_BIG;
    if (i < Z_BIG)  { ((float4*)d_hA)[i]    = z; return; } i -= Z_BIG;
    if (i < Z_BIG)  { ((float4*)d_hB)[i]    = z; return; } i -= Z_BIG;
    if (i < Z_BIG)  { ((float4*)d_hC)[i]    = z; return; } i -= Z_BIG;
    if (i < Z_CNT)  { ((float4*)d_cnt)[i]   = z; return; } i -= Z_CNT;
    ((float4*)d_deg_s)[i] = z;
}

// ---------------- degree ----------------
__global__ void k_deg(const void* __restrict__ ei, int E, float* __restrict__ deg) {
    int e = blockIdx.x * blockDim.x + threadIdx.x;
    if (e >= E) return;
    int dst;
    if (d_is64) dst = (int)((const long long*)ei)[(long long)E + e];
    else        dst = ((const int*)ei)[E + e];
    atomicAdd(&deg[dst], 1.0f);
}

__global__ void k_dinv(float* __restrict__ deg, int n) {
    int i = blockIdx.x * blockDim.x + threadIdx.x;
    if (i >= n) return;
    float d = deg[i];
    deg[i] = (d > 0.0f) ? rsqrtf(d) : 0.0f;
}

// ---------------- 5-dim normalized propagation (TAG1) ----------------
__global__ void k_prop5(const void* __restrict__ ei, int E,
                        const float* __restrict__ dinv,
                        const float* __restrict__ hin,
                        float* __restrict__ hout) {
    int e = blockIdx.x * blockDim.x + threadIdx.x;
    if (e >= E) return;
    int is64 = d_is64;
    int s, d;
    load_edge(ei, E, e, is64, s, d);
    float norm = dinv[s] * dinv[d];
    if (norm == 0.0f) return;
    const float* src = hin + (long long)s * DGG;
    float* dst = hout + (long long)d * DGG;
#pragma unroll
    for (int f = 0; f < DGG; f++) atomicAdd(dst + f, src[f] * norm);
}

// ---------------- 64-dim normalized propagation (TAG2) ----------------
// 8 threads/edge, 8 floats each: 2 float4 gathers + 2 vector REDs.
__global__ void k_prop64(const void* __restrict__ ei, int E,
                         const float* __restrict__ dinv,
                         const float* __restrict__ hin,
                         float* __restrict__ hout) {
    long long t = (long long)blockIdx.x * blockDim.x + threadIdx.x;
    int e = (int)(t >> 3);
    if (e >= E) return;
    int c = ((int)t & 7) << 3;
    int is64 = d_is64;
    int s, d;
    load_edge(ei, E, e, is64, s, d);
    float norm = dinv[s] * dinv[d];
    if (norm == 0.0f) return;
    const float4* src = (const float4*)(hin + (long long)s * HH + c);
    float4 v0 = src[0], v1 = src[1];
    float* o = hout + (long long)d * HH + c;
    red4(o,     v0.x * norm, v0.y * norm, v0.z * norm, v0.w * norm);
    red4(o + 4, v1.x * norm, v1.y * norm, v1.z * norm, v1.w * norm);
}

// ---------------- GraphConv aggregation: agg[dst] += w[e]*gx[src] ----------------
__global__ void k_gc_agg(const void* __restrict__ ei, int E,
                         const float* __restrict__ attr,
                         const float* __restrict__ gx,
                         float* __restrict__ agg) {
    long long t = (long long)blockIdx.x * blockDim.x + threadIdx.x;
    int e = (int)(t >> 3);
    if (e >= E) return;
    int c = ((int)t & 7) << 3;
    int is64 = d_is64;
    int s, d;
    load_edge(ei, E, e, is64, s, d);
    float w = attr[e];
    const float4* src = (const float4*)(gx + (long long)s * HH + c);
    float4 v0 = src[0], v1 = src[1];
    float* o = agg + (long long)d * HH + c;
    red4(o,     v0.x * w, v0.y * w, v0.z * w, v0.w * w);
    red4(o + 4, v1.x * w, v1.y * w, v1.z * w, v1.w * w);
}

// ---------------- SAGE aggregation: ssum[dst] += gx[src]; cnt[dst] += 1 ----------------
__global__ void k_sage_agg(const void* __restrict__ ei, int E,
                           const float* __restrict__ gx,
                           float* __restrict__ ssum,
                           float* __restrict__ cnt) {
    long long t = (long long)blockIdx.x * blockDim.x + threadIdx.x;
    int e = (int)(t >> 3);
    if (e >= E) return;
    int c = ((int)t & 7) << 3;
    int is64 = d_is64;
    int s, d;
    load_edge(ei, E, e, is64, s, d);
    const float4* src = (const float4*)(gx + (long long)s * HH + c);
    float4 v0 = src[0], v1 = src[1];
    float* o = ssum + (long long)d * HH + c;
    red4(o,     v0.x, v0.y, v0.z, v0.w);
    red4(o + 4, v1.x, v1.y, v1.z, v1.w);
    if (c == 0) atomicAdd(&cnt[d], 1.0f);
}

// ---------------- TAG1 dense: gx = relu(x@W0 + h1@W1 + h2@W2 + b) ----------------
__global__ void k_tag1_dense(const float* __restrict__ x,
                             const float* __restrict__ h1,
                             const float* __restrict__ h2,
                             const float* __restrict__ W,  // [3][5][64]
                             const float* __restrict__ b,
                             float* __restrict__ gx, int n) {
    __shared__ float sW[3 * DGG * HH];
    __shared__ float sb[HH];
    __shared__ float sX[32][16];
    int t = threadIdx.x;
    int base = blockIdx.x * 32;
    for (int i = t; i < 3 * DGG * HH; i += 256) sW[i] = W[i];
    if (t < HH) sb[t] = b[t];
    for (int i = t; i < 32 * 15; i += 256) {
        int row = i / 15, f = i - row * 15;
        int r = base + row;
        float v = 0.0f;
        if (r < n) {
            if (f < 5)       v = x [(long long)r * DGG + f];
            else if (f < 10) v = h1[(long long)r * DGG + (f - 5)];
            else             v = h2[(long long)r * DGG + (f - 10)];
        }
        sX[row][f] = v;
    }
    __syncthreads();
    int c = t & 63, ry = t >> 6;
#pragma unroll
    for (int j = 0; j < 8; j++) {
        int rl = ry + 4 * j;
        int r = base + rl;
        if (r >= n) continue;
        float acc = sb[c];
#pragma unroll
        for (int f = 0; f < DGG; f++) acc += sX[rl][f]      * sW[f * HH + c];
#pragma unroll
        for (int f = 0; f < DGG; f++) acc += sX[rl][5 + f]  * sW[(DGG + f) * HH + c];
#pragma unroll
        for (int f = 0; f < DGG; f++) acc += sX[rl][10 + f] * sW[(2 * DGG + f) * HH + c];
        gx[(long long)r * HH + c] = fmaxf(acc, 0.0f);
    }
}

// ---------------- GraphConv combine: sx = relu(agg@Wrel + b + state_x@Wroot) ----------------
__global__ void k_gc_comb(const float* __restrict__ agg,
                          const float* __restrict__ Wrel,
                          const float* __restrict__ b,
                          const float* __restrict__ statex,
                          const float* __restrict__ Wroot,
                          float* __restrict__ sx, int n) {
    __shared__ float sW1[HH * HH];
    __shared__ float sW2[DSS * HH];
    __shared__ float sb[HH];
    __shared__ float sA[32][HH];
    __shared__ float sS[32][8];
    int t = threadIdx.x;
    int base = blockIdx.x * 32;
    for (int i = t; i < HH * HH; i += 256) sW1[i] = Wrel[i];
    for (int i = t; i < DSS * HH; i += 256) sW2[i] = Wroot[i];
    if (t < HH) sb[t] = b[t];
    for (int i = t; i < 32 * HH; i += 256) {
        int row = i >> 6, col = i & 63, r = base + row;
        sA[row][col] = (r < n) ? agg[(long long)r * HH + col] : 0.0f;
    }
    for (int i = t; i < 32 * DSS; i += 256) {
        int row = i / DSS, col = i - row * DSS, r = base + row;
        sS[row][col] = (r < n) ? statex[(long long)r * DSS + col] : 0.0f;
    }
    __syncthreads();
    int c = t & 63, ry = t >> 6;
#pragma unroll
    for (int j = 0; j < 8; j++) {
        int rl = ry + 4 * j;
        int r = base + rl;
        if (r >= n) continue;
        float acc = sb[c];
#pragma unroll
        for (int k = 0; k < HH; k++) acc += sA[rl][k] * sW1[k * HH + c];
#pragma unroll
        for (int k = 0; k < DSS; k++) acc += sS[rl][k] * sW2[k * HH + c];
        sx[(long long)r * HH + c] = fmaxf(acc, 0.0f);
    }
}

// ---------------- SAGE combine: sx2 = relu(mean@Wl + bl + sx@Wr) ----------------
__global__ void k_sage_comb(const float* __restrict__ ssum,
                            const float* __restrict__ cnt,
                            const float* __restrict__ Wl,
                            const float* __restrict__ bl,
                            const float* __restrict__ sxin,
                            const float* __restrict__ Wr,
                            float* __restrict__ sx2, int n) {
    __shared__ float sW[HH * HH];
    __shared__ float sA[32][HH];
    __shared__ float sB[32][HH];
    int t = threadIdx.x;
    int base = blockIdx.x * 32;
    for (int i = t; i < HH * HH; i += 256) sW[i] = Wl[i];
    for (int i = t; i < 32 * HH; i += 256) {
        int row = i >> 6, col = i & 63, r = base + row;
        float vA = 0.0f, vB = 0.0f;
        if (r < n) {
            float cinv = 1.0f / fmaxf(cnt[r], 1.0f);
            vA = ssum[(long long)r * HH + col] * cinv;
            vB = sxin[(long long)r * HH + col];
        }
        sA[row][col] = vA;
        sB[row][col] = vB;
    }
    __syncthreads();
    int c = t & 63, ry = t >> 6;
    float acc[8];
#pragma unroll
    for (int j = 0; j < 8; j++) acc[j] = __ldg(&bl[c]);
#pragma unroll
    for (int j = 0; j < 8; j++) {
        int rl = ry + 4 * j;
#pragma unroll
        for (int k = 0; k < HH; k++) acc[j] += sA[rl][k] * sW[k * HH + c];
    }
    __syncthreads();
    for (int i = t; i < HH * HH; i += 256) sW[i] = Wr[i];
    __syncthreads();
#pragma unroll
    for (int j = 0; j < 8; j++) {
        int rl = ry + 4 * j;
        int r = base + rl;
#pragma unroll
        for (int k = 0; k < HH; k++) acc[j] += sB[rl][k] * sW[k * HH + c];
        if (r < n) sx2[(long long)r * HH + c] = fmaxf(acc[j], 0.0f);
    }
}

// ---------------- acc = X@W (+b) or acc += X@W ----------------
__global__ void k_mm(const float* __restrict__ X, const float* __restrict__ W,
                     const float* __restrict__ b, float* __restrict__ out,
                     int n, int add) {
    __shared__ float sW[HH * HH];
    __shared__ float sX[32][HH];
    __shared__ float sb[HH];
    int t = threadIdx.x;
    int base = blockIdx.x * 32;
    for (int i = t; i < HH * HH; i += 256) sW[i] = W[i];
    if (t < HH) sb[t] = b ? b[t] : 0.0f;
    for (int i = t; i < 32 * HH; i += 256) {
        int row = i >> 6, col = i & 63, r = base + row;
        sX[row][col] = (r < n) ? X[(long long)r * HH + col] : 0.0f;
    }
    __syncthreads();
    int c = t & 63, ry = t >> 6;
#pragma unroll
    for (int j = 0; j < 8; j++) {
        int rl = ry + 4 * j;
        int r = base + rl;
        if (r >= n) continue;
        float acc = sb[c];
#pragma unroll
        for (int k = 0; k < HH; k++) acc += sX[rl][k] * sW[k * HH + c];
        long long oi = (long long)r * HH + c;
        out[oi] = add ? (out[oi] + acc) : acc;
    }
}

// ---------------- final: out = relu(acc)@linW + linb ----------------
__global__ void k_final(const float* __restrict__ acc,
                        const float* __restrict__ W,
                        const float* __restrict__ b,
                        float* __restrict__ out, int n) {
    __shared__ float sA[32][HH];
    __shared__ float sW[HH * OUTD];
    __shared__ float sb[OUTD];
    int t = threadIdx.x;
    int base = blockIdx.x * 32;
    for (int i = t; i < HH * OUTD; i += 256) sW[i] = W[i];
    if (t < OUTD) sb[t] = b[t];
    for (int i = t; i < 32 * HH; i += 256) {
        int row = i >> 6, col = i & 63, r = base + row;
        sA[row][col] = (r < n) ? fmaxf(acc[(long long)r * HH + col], 0.0f) : 0.0f;
    }
    __syncthreads();
    int o = t & 7, ry = t >> 3;
    int r = base + ry;
    if (r >= n) return;
    float a = sb[o];
#pragma unroll
    for (int k = 0; k < HH; k++) a += sA[ry][k] * sW[k * OUTD + o];
    out[(long long)r * OUTD + o] = a;
}

// ---------------- host ----------------
static inline int gs(long long n, int bs) { return (int)((n + bs - 1) / bs); }

extern "C" void kernel_launch(void* const* d_in, const int* in_sizes, int n_in,
                              void* d_out, int out_size) {
    const float* game_x  = (const float*)d_in[0];
    const float* state_x = (const float*)d_in[1];
    const void*  ei_vv   = d_in[2];
    const void*  ei_h    = d_in[3];
    const float* attr_h  = (const float*)d_in[4];
    const void*  ei_in   = d_in[5];
    const void*  ei_ss   = d_in[6];
    const float* tag1W   = (const float*)d_in[7];
    const float* tag1b   = (const float*)d_in[8];
    const float* tag2W   = (const float*)d_in[9];
    const float* tag2b   = (const float*)d_in[10];
    const float* Wrel    = (const float*)d_in[11];
    const float* bgc     = (const float*)d_in[12];
    const float* Wroot   = (const float*)d_in[13];
    const float* Wl      = (const float*)d_in[14];
    const float* bl      = (const float*)d_in[15];
    const float* Wr      = (const float*)d_in[16];
    const float* linW    = (const float*)d_in[17];
    const float* linb    = (const float*)d_in[18];
    float* out = (float*)d_out;

    int nv  = in_sizes[0] / DGG;   // 100000
    int ns  = in_sizes[1] / DSS;   // 50000
    int Evv = in_sizes[2] / 2;
    int Eh  = in_sizes[3] / 2;
    int Ein = in_sizes[5] / 2;
    int Ess = in_sizes[6] / 2;

    float *deg_v, *h1, *h2, *gx, *agg, *ssum, *cnt, *deg_s, *sx, *sx2, *hA, *hB, *hC, *acc;
    cudaGetSymbolAddress((void**)&deg_v, d_deg_v);
    cudaGetSymbolAddress((void**)&h1, d_h1);
    cudaGetSymbolAddress((void**)&h2, d_h2);
    cudaGetSymbolAddress((void**)&gx, d_gx);
    cudaGetSymbolAddress((void**)&agg, d_agg);
    cudaGetSymbolAddress((void**)&ssum, d_ssum);
    cudaGetSymbolAddress((void**)&cnt, d_cnt);
    cudaGetSymbolAddress((void**)&deg_s, d_deg_s);
    cudaGetSymbolAddress((void**)&sx, d_sx);
    cudaGetSymbolAddress((void**)&sx2, d_sx2);
    cudaGetSymbolAddress((void**)&hA, d_hA);
    cudaGetSymbolAddress((void**)&hB, d_hB);
    cudaGetSymbolAddress((void**)&hC, d_hC);
    cudaGetSymbolAddress((void**)&acc, d_acc);

    const int BS = 256;

    // dtype probe (parallel) + all zeroing in one kernel
    k_detect<<<1, 32>>>((const int*)ei_vv);
    k_zero_all<<<gs(Z_TOTAL, BS), BS>>>();

    // ---- TAG1 on v-v graph ----
    k_deg<<<gs(Evv, BS), BS>>>(ei_vv, Evv, deg_v);
    k_dinv<<<gs(nv, BS), BS>>>(deg_v, nv);
    k_prop5<<<gs(Evv, BS), BS>>>(ei_vv, Evv, deg_v, game_x, h1);
    k_prop5<<<gs(Evv, BS), BS>>>(ei_vv, Evv, deg_v, h1, h2);
    k_tag1_dense<<<gs(nv, 32), BS>>>(game_x, h1, h2, tag1W, tag1b, gx, nv);

    // ---- GraphConv + SAGE aggregations ----
    k_gc_agg<<<gs((long long)Eh * 8, BS), BS>>>(ei_h, Eh, attr_h, gx, agg);
    k_sage_agg<<<gs((long long)Ein * 8, BS), BS>>>(ei_in, Ein, gx, ssum, cnt);

    k_gc_comb<<<gs(ns, 32), BS>>>(agg, Wrel, bgc, state_x, Wroot, sx, ns);
    k_sage_comb<<<gs(ns, 32), BS>>>(ssum, cnt, Wl, bl, sx, Wr, sx2, ns);

    // ---- TAG2 on s-s graph ----
    k_deg<<<gs(Ess, BS), BS>>>(ei_ss, Ess, deg_s);
    k_dinv<<<gs(ns, BS), BS>>>(deg_s, ns);

    // acc = sx2@W0 + b
    k_mm<<<gs(ns, 32), BS>>>(sx2, tag2W, tag2b, acc, ns, 0);

    k_prop64<<<gs((long long)Ess * 8, BS), BS>>>(ei_ss, Ess, deg_s, sx2, hA);
    k_mm<<<gs(ns, 32), BS>>>(hA, tag2W + 1 * HH * HH, (const float*)0, acc, ns, 1);

    k_prop64<<<gs((long long)Ess * 8, BS), BS>>>(ei_ss, Ess, deg_s, hA, hB);
    k_mm<<<gs(ns, 32), BS>>>(hB, tag2W + 2 * HH * HH, (const float*)0, acc, ns, 1);

    k_prop64<<<gs((long long)Ess * 8, BS), BS>>>(ei_ss, Ess, deg_s, hB, hC);
    k_mm<<<gs(ns, 32), BS>>>(hC, tag2W + 3 * HH * HH, (const float*)0, acc, ns, 1);

    // ---- final linear ----
    k_final<<<gs(ns, 32), BS>>>(acc, linW, linb, out, ns);
}

// round 5
// speedup vs baseline: 1.4032x; 1.0238x over previous
#include <cuda_runtime.h>

#define NVV 100000
#define NSS 50000
#define DGG 5
#define DSS 6
#define HH  64
#define OUTD 8
#define EVV_MAX 1000000
#define EH_MAX  1000000
#define EIN_MAX 500000
#define ESS_MAX 1000000

// ---------------- scratch (device globals; no allocations) ----------------
__device__ __align__(16) float d_h1[NVV * DGG];
__device__ __align__(16) float d_h2[NVV * DGG];
__device__ __align__(16) float d_gx[NVV * HH];
__device__ __align__(16) float d_agg[NSS * HH];
__device__ __align__(16) float d_ssum[NSS * HH];
__device__ __align__(16) float d_dinv_v[NVV];
__device__ __align__(16) float d_dinv_s[NSS];
__device__ __align__(16) float d_sx[NSS * HH];
__device__ __align__(16) float d_sx2[NSS * HH];
__device__ __align__(16) float d_hA[NSS * HH];
__device__ __align__(16) float d_hB[NSS * HH];
__device__ __align__(16) float d_hC[NSS * HH];
__device__ __align__(16) float d_acc[NSS * HH];
// CSR structures
__device__ __align__(16) int   d_cnt_vv[NVV];
__device__ __align__(16) int   d_cnt_h [NSS];
__device__ __align__(16) int   d_cnt_in[NSS];
__device__ __align__(16) int   d_cnt_ss[NSS];
__device__ __align__(16) int   d_rp_vv[NVV];
__device__ __align__(16) int   d_rp_h [NSS];
__device__ __align__(16) int   d_rp_in[NSS];
__device__ __align__(16) int   d_rp_ss[NSS];
__device__ __align__(16) int   d_cur_vv[NVV];
__device__ __align__(16) int   d_cur_h [NSS];
__device__ __align__(16) int   d_cur_in[NSS];
__device__ __align__(16) int   d_cur_ss[NSS];
__device__ __align__(16) int   d_cs_vv[EVV_MAX];
__device__ __align__(16) int   d_cs_h [EH_MAX];
__device__ __align__(16) float d_cw_h [EH_MAX];
__device__ __align__(16) int   d_cs_in[EIN_MAX];
__device__ __align__(16) int   d_cs_ss[ESS_MAX];
__device__ int d_is64;

// ---------------- dtype detection (parallel, 1 warp) ----------------
// Reference casts edge indices to int64; with JAX x64 disabled they stay int32.
// For int64 values < 2^31 every odd 32-bit word is 0.
__global__ void k_detect(const int* __restrict__ w) {
    int lane = threadIdx.x;
    int bad = 0;
    for (int i = lane; i < 128; i += 32)
        if (w[2 * i + 1] != 0) bad = 1;
    unsigned m = __ballot_sync(0xffffffffu, bad);
    if (lane == 0) d_is64 = (m == 0u) ? 1 : 0;
}

__device__ __forceinline__ void load_edge(const void* ei, int E, int e, int is64,
                                          int& s, int& d) {
    if (is64) {
        const long long* p = (const long long*)ei;
        s = (int)p[e];
        d = (int)p[(long long)E + e];
    } else {
        const int* p = (const int*)ei;
        s = p[e];
        d = p[E + e];
    }
}

// ---------------- zero the four histogram arrays ----------------
#define ZC_TOT (NVV + 3 * NSS)
__global__ void k_zero_cnts() {
    int i = blockIdx.x * blockDim.x + threadIdx.x;
    if (i >= ZC_TOT) return;
    if (i < NVV) { d_cnt_vv[i] = 0; return; } i -= NVV;
    if (i < NSS) { d_cnt_h[i]  = 0; return; } i -= NSS;
    if (i < NSS) { d_cnt_in[i] = 0; return; } i -= NSS;
    d_cnt_ss[i] = 0;
}

// ---------------- histogram over destinations (= degrees) ----------------
__global__ void k_hist(const void* __restrict__ ei, int E, int* __restrict__ cnt) {
    int e = blockIdx.x * blockDim.x + threadIdx.x;
    if (e >= E) return;
    int s, d;
    load_edge(ei, E, e, d_is64, s, d);
    atomicAdd(&cnt[d], 1);
}

// ---------------- single-block exclusive scan (n <= 100000) ----------------
__global__ void k_scan(const int* __restrict__ cnt, int n,
                       int* __restrict__ rp, int* __restrict__ cur) {
    __shared__ int wsum[32];
    __shared__ int running;
    int t = threadIdx.x;
    if (t == 0) running = 0;
    __syncthreads();
    for (int base = 0; base < n; base += 1024) {
        int i = base + t;
        int v = (i < n) ? cnt[i] : 0;
        int x = v;
#pragma unroll
        for (int o = 1; o < 32; o <<= 1) {
            int y = __shfl_up_sync(0xffffffffu, x, o);
            if ((t & 31) >= o) x += y;
        }
        if ((t & 31) == 31) wsum[t >> 5] = x;
        __syncthreads();
        if (t < 32) {
            int wv = wsum[t];
#pragma unroll
            for (int o = 1; o < 32; o <<= 1) {
                int y = __shfl_up_sync(0xffffffffu, wv, o);
                if (t >= o) wv += y;
            }
            wsum[t] = wv;
        }
        __syncthreads();
        int excl = x - v + ((t >> 5) ? wsum[(t >> 5) - 1] : 0) + running;
        if (i < n) { rp[i] = excl; cur[i] = excl; }
        __syncthreads();
        if (t == 0) running += wsum[31];
        __syncthreads();
    }
}

// ---------------- dinv from integer degree ----------------
__global__ void k_dinv(const int* __restrict__ cnt, float* __restrict__ dinv, int n) {
    int i = blockIdx.x * blockDim.x + threadIdx.x;
    if (i >= n) return;
    int c = cnt[i];
    dinv[i] = (c > 0) ? rsqrtf((float)c) : 0.0f;
}

// ---------------- CSR fill ----------------
__global__ void k_fill(const void* __restrict__ ei, int E,
                       int* __restrict__ cur, int* __restrict__ cs) {
    int e = blockIdx.x * blockDim.x + threadIdx.x;
    if (e >= E) return;
    int s, d;
    load_edge(ei, E, e, d_is64, s, d);
    int p = atomicAdd(&cur[d], 1);
    cs[p] = s;
}

__global__ void k_fillw(const void* __restrict__ ei, const float* __restrict__ attr,
                        int E, int* __restrict__ cur,
                        int* __restrict__ cs, float* __restrict__ cw) {
    int e = blockIdx.x * blockDim.x + threadIdx.x;
    if (e >= E) return;
    int s, d;
    load_edge(ei, E, e, d_is64, s, d);
    int p = atomicAdd(&cur[d], 1);
    cs[p] = s;
    cw[p] = attr[e];
}

// ---------------- 5-dim normalized gather (TAG1): 8 threads/row ----------------
__global__ void k_g5(const int* __restrict__ rp, const int* __restrict__ cnt,
                     const int* __restrict__ cs, const float* __restrict__ dinv,
                     const float* __restrict__ hin, float* __restrict__ hout, int n) {
    int t = blockIdx.x * blockDim.x + threadIdx.x;
    int row = t >> 3, f = t & 7;
    if (row >= n) return;
    int beg = rp[row], m = cnt[row];
    float dr = dinv[row];
    float acc = 0.0f;
    if (f < 5) {
        for (int j = 0; j < m; j++) {
            int s = cs[beg + j];
            acc += hin[s * DGG + f] * (dr * dinv[s]);
        }
        hout[row * DGG + f] = acc;
    }
}

// ---------------- 64-dim gathers: warp per row, float2 per lane ----------------
__global__ void k_gnorm64(const int* __restrict__ rp, const int* __restrict__ cnt,
                          const int* __restrict__ cs, const float* __restrict__ dinv,
                          const float* __restrict__ hin, float* __restrict__ hout, int n) {
    int w = (blockIdx.x * blockDim.x + threadIdx.x) >> 5;
    if (w >= n) return;
    int lane = threadIdx.x & 31;
    int beg = rp[w], m = cnt[w];
    float dr = dinv[w];
    float2 acc = make_float2(0.f, 0.f);
    const float2* base = (const float2*)hin;
#pragma unroll 4
    for (int j = 0; j < m; j++) {
        int s = cs[beg + j];
        float nm = dr * dinv[s];
        float2 v = base[(long long)s * 32 + lane];
        acc.x += v.x * nm;
        acc.y += v.y * nm;
    }
    ((float2*)hout)[(long long)w * 32 + lane] = acc;
}

__global__ void k_gw64(const int* __restrict__ rp, const int* __restrict__ cnt,
                       const int* __restrict__ cs, const float* __restrict__ cw,
                       const float* __restrict__ hin, float* __restrict__ hout, int n) {
    int w = (blockIdx.x * blockDim.x + threadIdx.x) >> 5;
    if (w >= n) return;
    int lane = threadIdx.x & 31;
    int beg = rp[w], m = cnt[w];
    float2 acc = make_float2(0.f, 0.f);
    const float2* base = (const float2*)hin;
#pragma unroll 4
    for (int j = 0; j < m; j++) {
        int s = cs[beg + j];
        float wt = cw[beg + j];
        float2 v = base[(long long)s * 32 + lane];
        acc.x += v.x * wt;
        acc.y += v.y * wt;
    }
    ((float2*)hout)[(long long)w * 32 + lane] = acc;
}

__global__ void k_gsum64(const int* __restrict__ rp, const int* __restrict__ cnt,
                         const int* __restrict__ cs,
                         const float* __restrict__ hin, float* __restrict__ hout, int n) {
    int w = (blockIdx.x * blockDim.x + threadIdx.x) >> 5;
    if (w >= n) return;
    int lane = threadIdx.x & 31;
    int beg = rp[w], m = cnt[w];
    float2 acc = make_float2(0.f, 0.f);
    const float2* base = (const float2*)hin;
#pragma unroll 4
    for (int j = 0; j < m; j++) {
        int s = cs[beg + j];
        float2 v = base[(long long)s * 32 + lane];
        acc.x += v.x;
        acc.y += v.y;
    }
    ((float2*)hout)[(long long)w * 32 + lane] = acc;
}

// ---------------- TAG1 dense: gx = relu(x@W0 + h1@W1 + h2@W2 + b) ----------------
__global__ void k_tag1_dense(const float* __restrict__ x,
                             const float* __restrict__ h1,
                             const float* __restrict__ h2,
                             const float* __restrict__ W,  // [3][5][64]
                             const float* __restrict__ b,
                             float* __restrict__ gx, int n) {
    __shared__ float sW[3 * DGG * HH];
    __shared__ float sb[HH];
    __shared__ float sX[32][16];
    int t = threadIdx.x;
    int base = blockIdx.x * 32;
    for (int i = t; i < 3 * DGG * HH; i += 256) sW[i] = W[i];
    if (t < HH) sb[t] = b[t];
    for (int i = t; i < 32 * 15; i += 256) {
        int row = i / 15, f = i - row * 15;
        int r = base + row;
        float v = 0.0f;
        if (r < n) {
            if (f < 5)       v = x [(long long)r * DGG + f];
            else if (f < 10) v = h1[(long long)r * DGG + (f - 5)];
            else             v = h2[(long long)r * DGG + (f - 10)];
        }
        sX[row][f] = v;
    }
    __syncthreads();
    int c = t & 63, ry = t >> 6;
#pragma unroll
    for (int j = 0; j < 8; j++) {
        int rl = ry + 4 * j;
        int r = base + rl;
        if (r >= n) continue;
        float acc = sb[c];
#pragma unroll
        for (int f = 0; f < DGG; f++) acc += sX[rl][f]      * sW[f * HH + c];
#pragma unroll
        for (int f = 0; f < DGG; f++) acc += sX[rl][5 + f]  * sW[(DGG + f) * HH + c];
#pragma unroll
        for (int f = 0; f < DGG; f++) acc += sX[rl][10 + f] * sW[(2 * DGG + f) * HH + c];
        gx[(long long)r * HH + c] = fmaxf(acc, 0.0f);
    }
}

// ---------------- GraphConv combine: sx = relu(agg@Wrel + b + state_x@Wroot) ----------------
__global__ void k_gc_comb(const float* __restrict__ agg,
                          const float* __restrict__ Wrel,
                          const float* __restrict__ b,
                          const float* __restrict__ statex,
                          const float* __restrict__ Wroot,
                          float* __restrict__ sx, int n) {
    __shared__ float sW1[HH * HH];
    __shared__ float sW2[DSS * HH];
    __shared__ float sb[HH];
    __shared__ float sA[32][HH];
    __shared__ float sS[32][8];
    int t = threadIdx.x;
    int base = blockIdx.x * 32;
    for (int i = t; i < HH * HH; i += 256) sW1[i] = Wrel[i];
    for (int i = t; i < DSS * HH; i += 256) sW2[i] = Wroot[i];
    if (t < HH) sb[t] = b[t];
    for (int i = t; i < 32 * HH; i += 256) {
        int row = i >> 6, col = i & 63, r = base + row;
        sA[row][col] = (r < n) ? agg[(long long)r * HH + col] : 0.0f;
    }
    for (int i = t; i < 32 * DSS; i += 256) {
        int row = i / DSS, col = i - row * DSS, r = base + row;
        sS[row][col] = (r < n) ? statex[(long long)r * DSS + col] : 0.0f;
    }
    __syncthreads();
    int c = t & 63, ry = t >> 6;
#pragma unroll
    for (int j = 0; j < 8; j++) {
        int rl = ry + 4 * j;
        int r = base + rl;
        if (r >= n) continue;
        float acc = sb[c];
#pragma unroll
        for (int k = 0; k < HH; k++) acc += sA[rl][k] * sW1[k * HH + c];
#pragma unroll
        for (int k = 0; k < DSS; k++) acc += sS[rl][k] * sW2[k * HH + c];
        sx[(long long)r * HH + c] = fmaxf(acc, 0.0f);
    }
}

// ---------------- SAGE combine: sx2 = relu(mean@Wl + bl + sx@Wr) ----------------
__global__ void k_sage_comb(const float* __restrict__ ssum,
                            const int* __restrict__ cnt,
                            const float* __restrict__ Wl,
                            const float* __restrict__ bl,
                            const float* __restrict__ sxin,
                            const float* __restrict__ Wr,
                            float* __restrict__ sx2, int n) {
    __shared__ float sW[HH * HH];
    __shared__ float sA[32][HH];
    __shared__ float sB[32][HH];
    int t = threadIdx.x;
    int base = blockIdx.x * 32;
    for (int i = t; i < HH * HH; i += 256) sW[i] = Wl[i];
    for (int i = t; i < 32 * HH; i += 256) {
        int row = i >> 6, col = i & 63, r = base + row;
        float vA = 0.0f, vB = 0.0f;
        if (r < n) {
            float cinv = 1.0f / fmaxf((float)cnt[r], 1.0f);
            vA = ssum[(long long)r * HH + col] * cinv;
            vB = sxin[(long long)r * HH + col];
        }
        sA[row][col] = vA;
        sB[row][col] = vB;
    }
    __syncthreads();
    int c = t & 63, ry = t >> 6;
    float acc[8];
#pragma unroll
    for (int j = 0; j < 8; j++) acc[j] = __ldg(&bl[c]);
#pragma unroll
    for (int j = 0; j < 8; j++) {
        int rl = ry + 4 * j;
#pragma unroll
        for (int k = 0; k < HH; k++) acc[j] += sA[rl][k] * sW[k * HH + c];
    }
    __syncthreads();
    for (int i = t; i < HH * HH; i += 256) sW[i] = Wr[i];
    __syncthreads();
#pragma unroll
    for (int j = 0; j < 8; j++) {
        int rl = ry + 4 * j;
        int r = base + rl;
#pragma unroll
        for (int k = 0; k < HH; k++) acc[j] += sB[rl][k] * sW[k * HH + c];
        if (r < n) sx2[(long long)r * HH + c] = fmaxf(acc[j], 0.0f);
    }
}

// ---------------- acc = X@W (+b) or acc += X@W ----------------
__global__ void k_mm(const float* __restrict__ X, const float* __restrict__ W,
                     const float* __restrict__ b, float* __restrict__ out,
                     int n, int add) {
    __shared__ float sW[HH * HH];
    __shared__ float sX[32][HH];
    __shared__ float sb[HH];
    int t = threadIdx.x;
    int base = blockIdx.x * 32;
    for (int i = t; i < HH * HH; i += 256) sW[i] = W[i];
    if (t < HH) sb[t] = b ? b[t] : 0.0f;
    for (int i = t; i < 32 * HH; i += 256) {
        int row = i >> 6, col = i & 63, r = base + row;
        sX[row][col] = (r < n) ? X[(long long)r * HH + col] : 0.0f;
    }
    __syncthreads();
    int c = t & 63, ry = t >> 6;
#pragma unroll
    for (int j = 0; j < 8; j++) {
        int rl = ry + 4 * j;
        int r = base + rl;
        if (r >= n) continue;
        float acc = sb[c];
#pragma unroll
        for (int k = 0; k < HH; k++) acc += sX[rl][k] * sW[k * HH + c];
        long long oi = (long long)r * HH + c;
        out[oi] = add ? (out[oi] + acc) : acc;
    }
}

// ---------------- final: out = relu(acc)@linW + linb ----------------
__global__ void k_final(const float* __restrict__ acc,
                        const float* __restrict__ W,
                        const float* __restrict__ b,
                        float* __restrict__ out, int n) {
    __shared__ float sA[32][HH];
    __shared__ float sW[HH * OUTD];
    __shared__ float sb[OUTD];
    int t = threadIdx.x;
    int base = blockIdx.x * 32;
    for (int i = t; i < HH * OUTD; i += 256) sW[i] = W[i];
    if (t < OUTD) sb[t] = b[t];
    for (int i = t; i < 32 * HH; i += 256) {
        int row = i >> 6, col = i & 63, r = base + row;
        sA[row][col] = (r < n) ? fmaxf(acc[(long long)r * HH + col], 0.0f) : 0.0f;
    }
    __syncthreads();
    int o = t & 7, ry = t >> 3;
    int r = base + ry;
    if (r >= n) return;
    float a = sb[o];
#pragma unroll
    for (int k = 0; k < HH; k++) a += sA[ry][k] * sW[k * OUTD + o];
    out[(long long)r * OUTD + o] = a;
}

// ---------------- host ----------------
static inline int gs(long long n, int bs) { return (int)((n + bs - 1) / bs); }

extern "C" void kernel_launch(void* const* d_in, const int* in_sizes, int n_in,
                              void* d_out, int out_size) {
    const float* game_x  = (const float*)d_in[0];
    const float* state_x = (const float*)d_in[1];
    const void*  ei_vv   = d_in[2];
    const void*  ei_h    = d_in[3];
    const float* attr_h  = (const float*)d_in[4];
    const void*  ei_in   = d_in[5];
    const void*  ei_ss   = d_in[6];
    const float* tag1W   = (const float*)d_in[7];
    const float* tag1b   = (const float*)d_in[8];
    const float* tag2W   = (const float*)d_in[9];
    const float* tag2b   = (const float*)d_in[10];
    const float* Wrel    = (const float*)d_in[11];
    const float* bgc     = (const float*)d_in[12];
    const float* Wroot   = (const float*)d_in[13];
    const float* Wl      = (const float*)d_in[14];
    const float* bl      = (const float*)d_in[15];
    const float* Wr      = (const float*)d_in[16];
    const float* linW    = (const float*)d_in[17];
    const float* linb    = (const float*)d_in[18];
    float* out = (float*)d_out;

    int nv  = in_sizes[0] / DGG;   // 100000
    int ns  = in_sizes[1] / DSS;   // 50000
    int Evv = in_sizes[2] / 2;
    int Eh  = in_sizes[3] / 2;
    int Ein = in_sizes[5] / 2;
    int Ess = in_sizes[6] / 2;

    float *h1, *h2, *gx, *agg, *ssum, *dinv_v, *dinv_s;
    float *sx, *sx2, *hA, *hB, *hC, *acc, *cw_h;
    int *cnt_vv, *cnt_h, *cnt_in, *cnt_ss;
    int *rp_vv, *rp_h, *rp_in, *rp_ss;
    int *cur_vv, *cur_h, *cur_in, *cur_ss;
    int *cs_vv, *cs_h, *cs_in, *cs_ss;
    cudaGetSymbolAddress((void**)&h1, d_h1);
    cudaGetSymbolAddress((void**)&h2, d_h2);
    cudaGetSymbolAddress((void**)&gx, d_gx);
    cudaGetSymbolAddress((void**)&agg, d_agg);
    cudaGetSymbolAddress((void**)&ssum, d_ssum);
    cudaGetSymbolAddress((void**)&dinv_v, d_dinv_v);
    cudaGetSymbolAddress((void**)&dinv_s, d_dinv_s);
    cudaGetSymbolAddress((void**)&sx, d_sx);
    cudaGetSymbolAddress((void**)&sx2, d_sx2);
    cudaGetSymbolAddress((void**)&hA, d_hA);
    cudaGetSymbolAddress((void**)&hB, d_hB);
    cudaGetSymbolAddress((void**)&hC, d_hC);
    cudaGetSymbolAddress((void**)&acc, d_acc);
    cudaGetSymbolAddress((void**)&cnt_vv, d_cnt_vv);
    cudaGetSymbolAddress((void**)&cnt_h, d_cnt_h);
    cudaGetSymbolAddress((void**)&cnt_in, d_cnt_in);
    cudaGetSymbolAddress((void**)&cnt_ss, d_cnt_ss);
    cudaGetSymbolAddress((void**)&rp_vv, d_rp_vv);
    cudaGetSymbolAddress((void**)&rp_h, d_rp_h);
    cudaGetSymbolAddress((void**)&rp_in, d_rp_in);
    cudaGetSymbolAddress((void**)&rp_ss, d_rp_ss);
    cudaGetSymbolAddress((void**)&cur_vv, d_cur_vv);
    cudaGetSymbolAddress((void**)&cur_h, d_cur_h);
    cudaGetSymbolAddress((void**)&cur_in, d_cur_in);
    cudaGetSymbolAddress((void**)&cur_ss, d_cur_ss);
    cudaGetSymbolAddress((void**)&cs_vv, d_cs_vv);
    cudaGetSymbolAddress((void**)&cs_h, d_cs_h);
    cudaGetSymbolAddress((void**)&cs_in, d_cs_in);
    cudaGetSymbolAddress((void**)&cs_ss, d_cs_ss);
    cudaGetSymbolAddress((void**)&cw_h, d_cw_h);

    const int BS = 256;

    // ---- probe + CSR builds ----
    k_detect<<<1, 32>>>((const int*)ei_vv);
    k_zero_cnts<<<gs(ZC_TOT, BS), BS>>>();
    k_hist<<<gs(Evv, BS), BS>>>(ei_vv, Evv, cnt_vv);
    k_hist<<<gs(Eh,  BS), BS>>>(ei_h,  Eh,  cnt_h);
    k_hist<<<gs(Ein, BS), BS>>>(ei_in, Ein, cnt_in);
    k_hist<<<gs(Ess, BS), BS>>>(ei_ss, Ess, cnt_ss);
    k_scan<<<1, 1024>>>(cnt_vv, nv, rp_vv, cur_vv);
    k_scan<<<1, 1024>>>(cnt_h,  ns, rp_h,  cur_h);
    k_scan<<<1, 1024>>>(cnt_in, ns, rp_in, cur_in);
    k_scan<<<1, 1024>>>(cnt_ss, ns, rp_ss, cur_ss);
    k_dinv<<<gs(nv, BS), BS>>>(cnt_vv, dinv_v, nv);
    k_dinv<<<gs(ns, BS), BS>>>(cnt_ss, dinv_s, ns);
    k_fill<<<gs(Evv, BS), BS>>>(ei_vv, Evv, cur_vv, cs_vv);
    k_fillw<<<gs(Eh, BS), BS>>>(ei_h, attr_h, Eh, cur_h, cs_h, cw_h);
    k_fill<<<gs(Ein, BS), BS>>>(ei_in, Ein, cur_in, cs_in);
    k_fill<<<gs(Ess, BS), BS>>>(ei_ss, Ess, cur_ss, cs_ss);

    // ---- TAG1 on v-v graph (CSR gathers) ----
    k_g5<<<gs((long long)nv * 8, BS), BS>>>(rp_vv, cnt_vv, cs_vv, dinv_v, game_x, h1, nv);
    k_g5<<<gs((long long)nv * 8, BS), BS>>>(rp_vv, cnt_vv, cs_vv, dinv_v, h1, h2, nv);
    k_tag1_dense<<<gs(nv, 32), BS>>>(game_x, h1, h2, tag1W, tag1b, gx, nv);

    // ---- GraphConv + SAGE aggregations (CSR gathers) ----
    k_gw64<<<gs((long long)ns * 32, BS), BS>>>(rp_h, cnt_h, cs_h, cw_h, gx, agg, ns);
    k_gsum64<<<gs((long long)ns * 32, BS), BS>>>(rp_in, cnt_in, cs_in, gx, ssum, ns);
    k_gc_comb<<<gs(ns, 32), BS>>>(agg, Wrel, bgc, state_x, Wroot, sx, ns);
    k_sage_comb<<<gs(ns, 32), BS>>>(ssum, cnt_in, Wl, bl, sx, Wr, sx2, ns);

    // ---- TAG2 on s-s graph ----
    k_mm<<<gs(ns, 32), BS>>>(sx2, tag2W, tag2b, acc, ns, 0);
    k_gnorm64<<<gs((long long)ns * 32, BS), BS>>>(rp_ss, cnt_ss, cs_ss, dinv_s, sx2, hA, ns);
    k_mm<<<gs(ns, 32), BS>>>(hA, tag2W + 1 * HH * HH, (const float*)0, acc, ns, 1);
    k_gnorm64<<<gs((long long)ns * 32, BS), BS>>>(rp_ss, cnt_ss, cs_ss, dinv_s, hA, hB, ns);
    k_mm<<<gs(ns, 32), BS>>>(hB, tag2W + 2 * HH * HH, (const float*)0, acc, ns, 1);
    k_gnorm64<<<gs((long long)ns * 32, BS), BS>>>(rp_ss, cnt_ss, cs_ss, dinv_s, hB, hC, ns);
    k_mm<<<gs(ns, 32), BS>>>(hC, tag2W + 3 * HH * HH, (const float*)0, acc, ns, 1);

    // ---- final linear ----
    k_final<<<gs(ns, 32), BS>>>(acc, linW, linb, out, ns);
}

// round 6
// speedup vs baseline: 1.9155x; 1.3651x over previous
#include <cuda_runtime.h>

#define NVV 100000
#define NSS 50000
#define DGG 5
#define DSS 6
#define HH  64
#define OUTD 8
#define EVV_MAX 1000000
#define EH_MAX  1000000
#define EIN_MAX 500000
#define ESS_MAX 1000000

#define NB_VV ((NVV + 1023) / 1024)   // 98
#define NB_S  ((NSS + 1023) / 1024)   // 49
#define NB_TOT (NB_VV + 3 * NB_S)     // 245

// ---------------- scratch (device globals; no allocations) ----------------
__device__ __align__(16) float d_h1[NVV * DGG];
__device__ __align__(16) float d_h2[NVV * DGG];
__device__ __align__(16) float d_gx[NVV * HH];
__device__ __align__(16) float d_agg[NSS * HH];
__device__ __align__(16) float d_ssum[NSS * HH];
__device__ __align__(16) float d_dinv_v[NVV];
__device__ __align__(16) float d_dinv_s[NSS];
__device__ __align__(16) float d_sx[NSS * HH];
__device__ __align__(16) float d_sx2[NSS * HH];
__device__ __align__(16) float d_hA[NSS * HH];
__device__ __align__(16) float d_hB[NSS * HH];
__device__ __align__(16) float d_hC[NSS * HH];
__device__ __align__(16) float d_acc[NSS * HH];
// CSR structures
__device__ __align__(16) int   d_cnt_vv[NVV];
__device__ __align__(16) int   d_cnt_h [NSS];
__device__ __align__(16) int   d_cnt_in[NSS];
__device__ __align__(16) int   d_cnt_ss[NSS];
__device__ __align__(16) int   d_rp_vv[NVV];
__device__ __align__(16) int   d_rp_h [NSS];
__device__ __align__(16) int   d_rp_in[NSS];
__device__ __align__(16) int   d_rp_ss[NSS];
__device__ __align__(16) int   d_cur_vv[NVV];
__device__ __align__(16) int   d_cur_h [NSS];
__device__ __align__(16) int   d_cur_in[NSS];
__device__ __align__(16) int   d_cur_ss[NSS];
__device__ __align__(16) int   d_cs_vv[EVV_MAX];
__device__ __align__(16) int   d_cs_h [EH_MAX];
__device__ __align__(16) float d_cw_h [EH_MAX];
__device__ __align__(16) int   d_cs_in[EIN_MAX];
__device__ __align__(16) int   d_cs_ss[ESS_MAX];
__device__ __align__(16) int   d_bsum[4 * 128];   // per-array block sums, padded
__device__ int d_is64;

// ---------------- dtype detection (parallel, 1 warp) ----------------
// Reference casts edge indices to int64; with JAX x64 disabled they stay int32.
// For int64 values < 2^31 every odd 32-bit word is 0.
__global__ void k_detect(const int* __restrict__ w) {
    int lane = threadIdx.x;
    int bad = 0;
    for (int i = lane; i < 128; i += 32)
        if (w[2 * i + 1] != 0) bad = 1;
    unsigned m = __ballot_sync(0xffffffffu, bad);
    if (lane == 0) d_is64 = (m == 0u) ? 1 : 0;
}

__device__ __forceinline__ void load_edge(const void* ei, int E, int e, int is64,
                                          int& s, int& d) {
    if (is64) {
        const long long* p = (const long long*)ei;
        s = (int)p[e];
        d = (int)p[(long long)E + e];
    } else {
        const int* p = (const int*)ei;
        s = p[e];
        d = p[E + e];
    }
}

// ---------------- zero the four histogram arrays ----------------
#define ZC_TOT (NVV + 3 * NSS)
__global__ void k_zero_cnts() {
    int i = blockIdx.x * blockDim.x + threadIdx.x;
    if (i >= ZC_TOT) return;
    if (i < NVV) { d_cnt_vv[i] = 0; return; } i -= NVV;
    if (i < NSS) { d_cnt_h[i]  = 0; return; } i -= NSS;
    if (i < NSS) { d_cnt_in[i] = 0; return; } i -= NSS;
    d_cnt_ss[i] = 0;
}

// ---------------- merged histogram over all 4 edge lists ----------------
__global__ void k_hist_all(const void* ei_vv, int Evv,
                           const void* ei_h,  int Eh,
                           const void* ei_in, int Ein,
                           const void* ei_ss, int Ess) {
    int t = blockIdx.x * blockDim.x + threadIdx.x;
    int is64 = d_is64;
    int s, d;
    if (t < Evv) {
        load_edge(ei_vv, Evv, t, is64, s, d);
        atomicAdd(&d_cnt_vv[d], 1);
        return;
    }
    t -= Evv;
    if (t < Eh) {
        load_edge(ei_h, Eh, t, is64, s, d);
        atomicAdd(&d_cnt_h[d], 1);
        return;
    }
    t -= Eh;
    if (t < Ein) {
        load_edge(ei_in, Ein, t, is64, s, d);
        atomicAdd(&d_cnt_in[d], 1);
        return;
    }
    t -= Ein;
    if (t < Ess) {
        load_edge(ei_ss, Ess, t, is64, s, d);
        atomicAdd(&d_cnt_ss[d], 1);
    }
}

// ---------------- phase A: per-1024-block exclusive scan + block sums ----------------
__device__ __forceinline__ void seg_of_block(int b, const int*& cnt, int*& rp,
                                             int& n, int& seg, int& lb) {
    if (b < NB_VV)                { cnt = d_cnt_vv; rp = d_rp_vv; n = NVV; seg = 0; lb = b; return; }
    b -= NB_VV;
    if (b < NB_S)                 { cnt = d_cnt_h;  rp = d_rp_h;  n = NSS; seg = 1; lb = b; return; }
    b -= NB_S;
    if (b < NB_S)                 { cnt = d_cnt_in; rp = d_rp_in; n = NSS; seg = 2; lb = b; return; }
    b -= NB_S;
    { cnt = d_cnt_ss; rp = d_rp_ss; n = NSS; seg = 3; lb = b; }
}

__global__ void k_blockscan() {
    const int* cnt; int* rp; int n, seg, lb;
    seg_of_block(blockIdx.x, cnt, rp, n, seg, lb);
    int t = threadIdx.x;
    int i = lb * 1024 + t;
    int v = (i < n) ? cnt[i] : 0;
    int x = v;
#pragma unroll
    for (int o = 1; o < 32; o <<= 1) {
        int y = __shfl_up_sync(0xffffffffu, x, o);
        if ((t & 31) >= o) x += y;
    }
    __shared__ int wsum[32];
    if ((t & 31) == 31) wsum[t >> 5] = x;
    __syncthreads();
    if (t < 32) {
        int wv = wsum[t];
#pragma unroll
        for (int o = 1; o < 32; o <<= 1) {
            int y = __shfl_up_sync(0xffffffffu, wv, o);
            if (t >= o) wv += y;
        }
        wsum[t] = wv;
    }
    __syncthreads();
    int excl = x - v + ((t >> 5) ? wsum[(t >> 5) - 1] : 0);
    if (i < n) rp[i] = excl;
    if (t == 1023) d_bsum[seg * 128 + lb] = excl + v;
}

// ---------------- phase B: scan the block sums (1 block, 4 segments x 128) ----------------
__global__ void k_scanpart() {
    int t = threadIdx.x;          // 0..511
    int seg = t >> 7;
    int i = t & 127;
    int len = (seg == 0) ? NB_VV : NB_S;
    int* base = d_bsum + seg * 128;
    int v = (i < len) ? base[i] : 0;
    int x = v;
#pragma unroll
    for (int o = 1; o < 32; o <<= 1) {
        int y = __shfl_up_sync(0xffffffffu, x, o);
        if ((t & 31) >= o) x += y;
    }
    __shared__ int ws[16];        // 4 segs x 4 warps
    int warp = (t >> 5) & 3;
    if ((t & 31) == 31) ws[seg * 4 + warp] = x;
    __syncthreads();
    if (i == 0) {
        int run = 0;
#pragma unroll
        for (int w = 0; w < 4; w++) {
            int tmp = ws[seg * 4 + w];
            ws[seg * 4 + w] = run;
            run += tmp;
        }
    }
    __syncthreads();
    int excl = x - v + ws[seg * 4 + warp];
    if (i < len) base[i] = excl;
}

// ---------------- phase C: add offsets, init cursors ----------------
__global__ void k_addoff() {
    const int* cnt; int* rp; int n, seg, lb;
    seg_of_block(blockIdx.x, cnt, rp, n, seg, lb);
    int i = lb * 1024 + threadIdx.x;
    if (i >= n) return;
    int off = d_bsum[seg * 128 + lb];
    int v = rp[i] + off;
    rp[i] = v;
    int* cur = (seg == 0) ? d_cur_vv : (seg == 1) ? d_cur_h : (seg == 2) ? d_cur_in : d_cur_ss;
    cur[i] = v;
}

// ---------------- dinv for both graphs in one launch ----------------
__global__ void k_dinv_all() {
    int i = blockIdx.x * blockDim.x + threadIdx.x;
    if (i < NVV) {
        int c = d_cnt_vv[i];
        d_dinv_v[i] = (c > 0) ? rsqrtf((float)c) : 0.0f;
        return;
    }
    i -= NVV;
    if (i < NSS) {
        int c = d_cnt_ss[i];
        d_dinv_s[i] = (c > 0) ? rsqrtf((float)c) : 0.0f;
    }
}

// ---------------- merged CSR fill over all 4 edge lists ----------------
__global__ void k_fill_all(const void* ei_vv, int Evv,
                           const void* ei_h,  int Eh, const float* __restrict__ attr,
                           const void* ei_in, int Ein,
                           const void* ei_ss, int Ess) {
    int t = blockIdx.x * blockDim.x + threadIdx.x;
    int is64 = d_is64;
    int s, d;
    if (t < Evv) {
        load_edge(ei_vv, Evv, t, is64, s, d);
        int p = atomicAdd(&d_cur_vv[d], 1);
        d_cs_vv[p] = s;
        return;
    }
    t -= Evv;
    if (t < Eh) {
        load_edge(ei_h, Eh, t, is64, s, d);
        int p = atomicAdd(&d_cur_h[d], 1);
        d_cs_h[p] = s;
        d_cw_h[p] = attr[t];
        return;
    }
    t -= Eh;
    if (t < Ein) {
        load_edge(ei_in, Ein, t, is64, s, d);
        int p = atomicAdd(&d_cur_in[d], 1);
        d_cs_in[p] = s;
        return;
    }
    t -= Ein;
    if (t < Ess) {
        load_edge(ei_ss, Ess, t, is64, s, d);
        int p = atomicAdd(&d_cur_ss[d], 1);
        d_cs_ss[p] = s;
    }
}

// ---------------- 5-dim normalized gather (TAG1): 8 threads/row ----------------
__global__ void k_g5(const int* __restrict__ rp, const int* __restrict__ cnt,
                     const int* __restrict__ cs, const float* __restrict__ dinv,
                     const float* __restrict__ hin, float* __restrict__ hout, int n) {
    int t = blockIdx.x * blockDim.x + threadIdx.x;
    int row = t >> 3, f = t & 7;
    if (row >= n) return;
    int beg = rp[row], m = cnt[row];
    float dr = dinv[row];
    float acc = 0.0f;
    if (f < 5) {
        for (int j = 0; j < m; j++) {
            int s = cs[beg + j];
            acc += hin[s * DGG + f] * (dr * dinv[s]);
        }
        hout[row * DGG + f] = acc;
    }
}

// ---------------- 64-dim gathers: warp per row, float2 per lane ----------------
__global__ void k_gnorm64(const int* __restrict__ rp, const int* __restrict__ cnt,
                          const int* __restrict__ cs, const float* __restrict__ dinv,
                          const float* __restrict__ hin, float* __restrict__ hout, int n) {
    int w = (blockIdx.x * blockDim.x + threadIdx.x) >> 5;
    if (w >= n) return;
    int lane = threadIdx.x & 31;
    int beg = rp[w], m = cnt[w];
    float dr = dinv[w];
    float2 acc = make_float2(0.f, 0.f);
    const float2* base = (const float2*)hin;
#pragma unroll 4
    for (int j = 0; j < m; j++) {
        int s = cs[beg + j];
        float nm = dr * dinv[s];
        float2 v = base[(long long)s * 32 + lane];
        acc.x += v.x * nm;
        acc.y += v.y * nm;
    }
    ((float2*)hout)[(long long)w * 32 + lane] = acc;
}

__global__ void k_gw64(const int* __restrict__ rp, const int* __restrict__ cnt,
                       const int* __restrict__ cs, const float* __restrict__ cw,
                       const float* __restrict__ hin, float* __restrict__ hout, int n) {
    int w = (blockIdx.x * blockDim.x + threadIdx.x) >> 5;
    if (w >= n) return;
    int lane = threadIdx.x & 31;
    int beg = rp[w], m = cnt[w];
    float2 acc = make_float2(0.f, 0.f);
    const float2* base = (const float2*)hin;
#pragma unroll 4
    for (int j = 0; j < m; j++) {
        int s = cs[beg + j];
        float wt = cw[beg + j];
        float2 v = base[(long long)s * 32 + lane];
        acc.x += v.x * wt;
        acc.y += v.y * wt;
    }
    ((float2*)hout)[(long long)w * 32 + lane] = acc;
}

__global__ void k_gsum64(const int* __restrict__ rp, const int* __restrict__ cnt,
                         const int* __restrict__ cs,
                         const float* __restrict__ hin, float* __restrict__ hout, int n) {
    int w = (blockIdx.x * blockDim.x + threadIdx.x) >> 5;
    if (w >= n) return;
    int lane = threadIdx.x & 31;
    int beg = rp[w], m = cnt[w];
    float2 acc = make_float2(0.f, 0.f);
    const float2* base = (const float2*)hin;
#pragma unroll 4
    for (int j = 0; j < m; j++) {
        int s = cs[beg + j];
        float2 v = base[(long long)s * 32 + lane];
        acc.x += v.x;
        acc.y += v.y;
    }
    ((float2*)hout)[(long long)w * 32 + lane] = acc;
}

// ---------------- TAG1 dense: gx = relu(x@W0 + h1@W1 + h2@W2 + b) ----------------
__global__ void k_tag1_dense(const float* __restrict__ x,
                             const float* __restrict__ h1,
                             const float* __restrict__ h2,
                             const float* __restrict__ W,  // [3][5][64]
                             const float* __restrict__ b,
                             float* __restrict__ gx, int n) {
    __shared__ float sW[3 * DGG * HH];
    __shared__ float sb[HH];
    __shared__ float sX[32][16];
    int t = threadIdx.x;
    int base = blockIdx.x * 32;
    for (int i = t; i < 3 * DGG * HH; i += 256) sW[i] = W[i];
    if (t < HH) sb[t] = b[t];
    for (int i = t; i < 32 * 15; i += 256) {
        int row = i / 15, f = i - row * 15;
        int r = base + row;
        float v = 0.0f;
        if (r < n) {
            if (f < 5)       v = x [(long long)r * DGG + f];
            else if (f < 10) v = h1[(long long)r * DGG + (f - 5)];
            else             v = h2[(long long)r * DGG + (f - 10)];
        }
        sX[row][f] = v;
    }
    __syncthreads();
    int c = t & 63, ry = t >> 6;
#pragma unroll
    for (int j = 0; j < 8; j++) {
        int rl = ry + 4 * j;
        int r = base + rl;
        if (r >= n) continue;
        float acc = sb[c];
#pragma unroll
        for (int f = 0; f < DGG; f++) acc += sX[rl][f]      * sW[f * HH + c];
#pragma unroll
        for (int f = 0; f < DGG; f++) acc += sX[rl][5 + f]  * sW[(DGG + f) * HH + c];
#pragma unroll
        for (int f = 0; f < DGG; f++) acc += sX[rl][10 + f] * sW[(2 * DGG + f) * HH + c];
        gx[(long long)r * HH + c] = fmaxf(acc, 0.0f);
    }
}

// ---------------- GraphConv combine: sx = relu(agg@Wrel + b + state_x@Wroot) ----------------
__global__ void k_gc_comb(const float* __restrict__ agg,
                          const float* __restrict__ Wrel,
                          const float* __restrict__ b,
                          const float* __restrict__ statex,
                          const float* __restrict__ Wroot,
                          float* __restrict__ sx, int n) {
    __shared__ float sW1[HH * HH];
    __shared__ float sW2[DSS * HH];
    __shared__ float sb[HH];
    __shared__ float sA[32][HH];
    __shared__ float sS[32][8];
    int t = threadIdx.x;
    int base = blockIdx.x * 32;
    for (int i = t; i < HH * HH; i += 256) sW1[i] = Wrel[i];
    for (int i = t; i < DSS * HH; i += 256) sW2[i] = Wroot[i];
    if (t < HH) sb[t] = b[t];
    for (int i = t; i < 32 * HH; i += 256) {
        int row = i >> 6, col = i & 63, r = base + row;
        sA[row][col] = (r < n) ? agg[(long long)r * HH + col] : 0.0f;
    }
    for (int i = t; i < 32 * DSS; i += 256) {
        int row = i / DSS, col = i - row * DSS, r = base + row;
        sS[row][col] = (r < n) ? statex[(long long)r * DSS + col] : 0.0f;
    }
    __syncthreads();
    int c = t & 63, ry = t >> 6;
#pragma unroll
    for (int j = 0; j < 8; j++) {
        int rl = ry + 4 * j;
        int r = base + rl;
        if (r >= n) continue;
        float acc = sb[c];
#pragma unroll
        for (int k = 0; k < HH; k++) acc += sA[rl][k] * sW1[k * HH + c];
#pragma unroll
        for (int k = 0; k < DSS; k++) acc += sS[rl][k] * sW2[k * HH + c];
        sx[(long long)r * HH + c] = fmaxf(acc, 0.0f);
    }
}

// ---------------- SAGE combine: sx2 = relu(mean@Wl + bl + sx@Wr) ----------------
__global__ void k_sage_comb(const float* __restrict__ ssum,
                            const int* __restrict__ cnt,
                            const float* __restrict__ Wl,
                            const float* __restrict__ bl,
                            const float* __restrict__ sxin,
                            const float* __restrict__ Wr,
                            float* __restrict__ sx2, int n) {
    __shared__ float sW[HH * HH];
    __shared__ float sA[32][HH];
    __shared__ float sB[32][HH];
    int t = threadIdx.x;
    int base = blockIdx.x * 32;
    for (int i = t; i < HH * HH; i += 256) sW[i] = Wl[i];
    for (int i = t; i < 32 * HH; i += 256) {
        int row = i >> 6, col = i & 63, r = base + row;
        float vA = 0.0f, vB = 0.0f;
        if (r < n) {
            float cinv = 1.0f / fmaxf((float)cnt[r], 1.0f);
            vA = ssum[(long long)r * HH + col] * cinv;
            vB = sxin[(long long)r * HH + col];
        }
        sA[row][col] = vA;
        sB[row][col] = vB;
    }
    __syncthreads();
    int c = t & 63, ry = t >> 6;
    float acc[8];
#pragma unroll
    for (int j = 0; j < 8; j++) acc[j] = __ldg(&bl[c]);
#pragma unroll
    for (int j = 0; j < 8; j++) {
        int rl = ry + 4 * j;
#pragma unroll
        for (int k = 0; k < HH; k++) acc[j] += sA[rl][k] * sW[k * HH + c];
    }
    __syncthreads();
    for (int i = t; i < HH * HH; i += 256) sW[i] = Wr[i];
    __syncthreads();
#pragma unroll
    for (int j = 0; j < 8; j++) {
        int rl = ry + 4 * j;
        int r = base + rl;
#pragma unroll
        for (int k = 0; k < HH; k++) acc[j] += sB[rl][k] * sW[k * HH + c];
        if (r < n) sx2[(long long)r * HH + c] = fmaxf(acc[j], 0.0f);
    }
}

// ---------------- acc = X@W (+b) or acc += X@W ----------------
__global__ void k_mm(const float* __restrict__ X, const float* __restrict__ W,
                     const float* __restrict__ b, float* __restrict__ out,
                     int n, int add) {
    __shared__ float sW[HH * HH];
    __shared__ float sX[32][HH];
    __shared__ float sb[HH];
    int t = threadIdx.x;
    int base = blockIdx.x * 32;
    for (int i = t; i < HH * HH; i += 256) sW[i] = W[i];
    if (t < HH) sb[t] = b ? b[t] : 0.0f;
    for (int i = t; i < 32 * HH; i += 256) {
        int row = i >> 6, col = i & 63, r = base + row;
        sX[row][col] = (r < n) ? X[(long long)r * HH + col] : 0.0f;
    }
    __syncthreads();
    int c = t & 63, ry = t >> 6;
#pragma unroll
    for (int j = 0; j < 8; j++) {
        int rl = ry + 4 * j;
        int r = base + rl;
        if (r >= n) continue;
        float acc = sb[c];
#pragma unroll
        for (int k = 0; k < HH; k++) acc += sX[rl][k] * sW[k * HH + c];
        long long oi = (long long)r * HH + c;
        out[oi] = add ? (out[oi] + acc) : acc;
    }
}

// ---------------- final: out = relu(acc)@linW + linb ----------------
__global__ void k_final(const float* __restrict__ acc,
                        const float* __restrict__ W,
                        const float* __restrict__ b,
                        float* __restrict__ out, int n) {
    __shared__ float sA[32][HH];
    __shared__ float sW[HH * OUTD];
    __shared__ float sb[OUTD];
    int t = threadIdx.x;
    int base = blockIdx.x * 32;
    for (int i = t; i < HH * OUTD; i += 256) sW[i] = W[i];
    if (t < OUTD) sb[t] = b[t];
    for (int i = t; i < 32 * HH; i += 256) {
        int row = i >> 6, col = i & 63, r = base + row;
        sA[row][col] = (r < n) ? fmaxf(acc[(long long)r * HH + col], 0.0f) : 0.0f;
    }
    __syncthreads();
    int o = t & 7, ry = t >> 3;
    int r = base + ry;
    if (r >= n) return;
    float a = sb[o];
#pragma unroll
    for (int k = 0; k < HH; k++) a += sA[ry][k] * sW[k * OUTD + o];
    out[(long long)r * OUTD + o] = a;
}

// ---------------- host ----------------
static inline int gs(long long n, int bs) { return (int)((n + bs - 1) / bs); }

extern "C" void kernel_launch(void* const* d_in, const int* in_sizes, int n_in,
                              void* d_out, int out_size) {
    const float* game_x  = (const float*)d_in[0];
    const float* state_x = (const float*)d_in[1];
    const void*  ei_vv   = d_in[2];
    const void*  ei_h    = d_in[3];
    const float* attr_h  = (const float*)d_in[4];
    const void*  ei_in   = d_in[5];
    const void*  ei_ss   = d_in[6];
    const float* tag1W   = (const float*)d_in[7];
    const float* tag1b   = (const float*)d_in[8];
    const float* tag2W   = (const float*)d_in[9];
    const float* tag2b   = (const float*)d_in[10];
    const float* Wrel    = (const float*)d_in[11];
    const float* bgc     = (const float*)d_in[12];
    const float* Wroot   = (const float*)d_in[13];
    const float* Wl      = (const float*)d_in[14];
    const float* bl      = (const float*)d_in[15];
    const float* Wr      = (const float*)d_in[16];
    const float* linW    = (const float*)d_in[17];
    const float* linb    = (const float*)d_in[18];
    float* out = (float*)d_out;

    int nv  = in_sizes[0] / DGG;   // 100000
    int ns  = in_sizes[1] / DSS;   // 50000
    int Evv = in_sizes[2] / 2;
    int Eh  = in_sizes[3] / 2;
    int Ein = in_sizes[5] / 2;
    int Ess = in_sizes[6] / 2;

    float *h1, *h2, *gx, *agg, *ssum, *dinv_v, *dinv_s;
    float *sx, *sx2, *hA, *hB, *hC, *acc, *cw_h;
    int *cnt_vv, *cnt_h, *cnt_in, *cnt_ss;
    int *rp_vv, *rp_h, *rp_in, *rp_ss;
    int *cs_vv, *cs_h, *cs_in, *cs_ss;
    cudaGetSymbolAddress((void**)&h1, d_h1);
    cudaGetSymbolAddress((void**)&h2, d_h2);
    cudaGetSymbolAddress((void**)&gx, d_gx);
    cudaGetSymbolAddress((void**)&agg, d_agg);
    cudaGetSymbolAddress((void**)&ssum, d_ssum);
    cudaGetSymbolAddress((void**)&dinv_v, d_dinv_v);
    cudaGetSymbolAddress((void**)&dinv_s, d_dinv_s);
    cudaGetSymbolAddress((void**)&sx, d_sx);
    cudaGetSymbolAddress((void**)&sx2, d_sx2);
    cudaGetSymbolAddress((void**)&hA, d_hA);
    cudaGetSymbolAddress((void**)&hB, d_hB);
    cudaGetSymbolAddress((void**)&hC, d_hC);
    cudaGetSymbolAddress((void**)&acc, d_acc);
    cudaGetSymbolAddress((void**)&cnt_vv, d_cnt_vv);
    cudaGetSymbolAddress((void**)&cnt_h, d_cnt_h);
    cudaGetSymbolAddress((void**)&cnt_in, d_cnt_in);
    cudaGetSymbolAddress((void**)&cnt_ss, d_cnt_ss);
    cudaGetSymbolAddress((void**)&rp_vv, d_rp_vv);
    cudaGetSymbolAddress((void**)&rp_h, d_rp_h);
    cudaGetSymbolAddress((void**)&rp_in, d_rp_in);
    cudaGetSymbolAddress((void**)&rp_ss, d_rp_ss);
    cudaGetSymbolAddress((void**)&cs_vv, d_cs_vv);
    cudaGetSymbolAddress((void**)&cs_h, d_cs_h);
    cudaGetSymbolAddress((void**)&cs_in, d_cs_in);
    cudaGetSymbolAddress((void**)&cs_ss, d_cs_ss);
    cudaGetSymbolAddress((void**)&cw_h, d_cw_h);

    const int BS = 256;
    long long Etot = (long long)Evv + Eh + Ein + Ess;

    // ---- probe + CSR builds ----
    k_detect<<<1, 32>>>((const int*)ei_vv);
    k_zero_cnts<<<gs(ZC_TOT, BS), BS>>>();
    k_hist_all<<<gs(Etot, BS), BS>>>(ei_vv, Evv, ei_h, Eh, ei_in, Ein, ei_ss, Ess);
    k_blockscan<<<NB_TOT, 1024>>>();
    k_scanpart<<<1, 512>>>();
    k_addoff<<<NB_TOT, 1024>>>();
    k_dinv_all<<<gs(NVV + NSS, BS), BS>>>();
    k_fill_all<<<gs(Etot, BS), BS>>>(ei_vv, Evv, ei_h, Eh, attr_h, ei_in, Ein, ei_ss, Ess);

    // ---- TAG1 on v-v graph (CSR gathers) ----
    k_g5<<<gs((long long)nv * 8, BS), BS>>>(rp_vv, cnt_vv, cs_vv, dinv_v, game_x, h1, nv);
    k_g5<<<gs((long long)nv * 8, BS), BS>>>(rp_vv, cnt_vv, cs_vv, dinv_v, h1, h2, nv);
    k_tag1_dense<<<gs(nv, 32), BS>>>(game_x, h1, h2, tag1W, tag1b, gx, nv);

    // ---- GraphConv + SAGE aggregations (CSR gathers) ----
    k_gw64<<<gs((long long)ns * 32, BS), BS>>>(rp_h, cnt_h, cs_h, cw_h, gx, agg, ns);
    k_gsum64<<<gs((long long)ns * 32, BS), BS>>>(rp_in, cnt_in, cs_in, gx, ssum, ns);
    k_gc_comb<<<gs(ns, 32), BS>>>(agg, Wrel, bgc, state_x, Wroot, sx, ns);
    k_sage_comb<<<gs(ns, 32), BS>>>(ssum, cnt_in, Wl, bl, sx, Wr, sx2, ns);

    // ---- TAG2 on s-s graph ----
    k_mm<<<gs(ns, 32), BS>>>(sx2, tag2W, tag2b, acc, ns, 0);
    k_gnorm64<<<gs((long long)ns * 32, BS), BS>>>(rp_ss, cnt_ss, cs_ss, dinv_s, sx2, hA, ns);
    k_mm<<<gs(ns, 32), BS>>>(hA, tag2W + 1 * HH * HH, (const float*)0, acc, ns, 1);
    k_gnorm64<<<gs((long long)ns * 32, BS), BS>>>(rp_ss, cnt_ss, cs_ss, dinv_s, hA, hB, ns);
    k_mm<<<gs(ns, 32), BS>>>(hB, tag2W + 2 * HH * HH, (const float*)0, acc, ns, 1);
    k_gnorm64<<<gs((long long)ns * 32, BS), BS>>>(rp_ss, cnt_ss, cs_ss, dinv_s, hB, hC, ns);
    k_mm<<<gs(ns, 32), BS>>>(hC, tag2W + 3 * HH * HH, (const float*)0, acc, ns, 1);

    // ---- final linear ----
    k_final<<<gs(ns, 32), BS>>>(acc, linW, linb, out, ns);
}